// round 7
// baseline (speedup 1.0000x reference)
#include <cuda_runtime.h>
#include <cuda_bf16.h>
#include <math.h>
#include <stdint.h>

#define BB 64
#define TT 512
#define DD 1024
#define HH 1024
#define VV 128
#define NCTA 128
#define NTHR 512
#define KC 128           // k elements per chunk
#define NCH 16           // chunks per phase (K = 2048)
#define PB 272           // bytes per staged row (128 bf16 + 8 pad)

// ---- dynamic smem layout (byte offsets) ----
#define ARR   17408          // one staged array: 64 rows * 272B
#define STAGE (4 * ARR)      // AH, AL, BH, BL
#define AH0   0
#define AL0   ARR
#define BH0   (2 * ARR)
#define BL0   (3 * ARR)
#define SGATE (2 * STAGE)              // 139264: f32 [64][68]
#define SCST  (SGATE + 64 * 68 * 4)    // f32 [64][17]
#define STOKS (SCST + 64 * 17 * 4)     // 64 ints
#define SMEM_DYN (STOKS + 256 + 256)

// ---- persistent device scratch ----
__device__ __nv_bfloat16 g_WBh[2ull * 64 * 64 * 2048];  // permuted weights hi
__device__ __nv_bfloat16 g_WBl[2ull * 64 * 64 * 2048];  // permuted weights lo
__device__ __nv_bfloat16 g_embh[VV * DD];
__device__ __nv_bfloat16 g_embl[VV * DD];
__device__ __nv_bfloat16 g_h0h[2][BB][HH];
__device__ __nv_bfloat16 g_h0l[2][BB][HH];
__device__ __nv_bfloat16 g_h1h[2][BB][HH];
__device__ __nv_bfloat16 g_h1l[2][BB][HH];
__device__ float g_Hout[(size_t)BB * TT * HH];
__device__ volatile unsigned g_gen;
__device__ unsigned g_count;

__device__ __forceinline__ float sigf(float v) { return 1.0f / (1.0f + expf(-v)); }

__device__ __forceinline__ uint32_t smem_u32(const void* p) {
    uint32_t a;
    asm("{ .reg .u64 t; cvta.to.shared.u64 t, %1; cvt.u32.u64 %0, t; }" : "=r"(a) : "l"(p));
    return a;
}
__device__ __forceinline__ void cp16(uint32_t dst, const void* src) {
    asm volatile("cp.async.cg.shared.global [%0], [%1], 16;" :: "r"(dst), "l"(src));
}
__device__ __forceinline__ void cp_commit() { asm volatile("cp.async.commit_group;"); }
template<int N> __device__ __forceinline__ void cp_wait() {
    asm volatile("cp.async.wait_group %0;" :: "n"(N));
}
__device__ __forceinline__ uint32_t lds_u32(uint32_t a) {
    uint32_t v; asm volatile("ld.shared.b32 %0, [%1];" : "=r"(v) : "r"(a)); return v;
}
__device__ __forceinline__ float lds_f32(uint32_t a) {
    float v; asm volatile("ld.shared.f32 %0, [%1];" : "=f"(v) : "r"(a)); return v;
}
__device__ __forceinline__ void sts_u32(uint32_t a, uint32_t v) {
    asm volatile("st.shared.b32 [%0], %1;" :: "r"(a), "r"(v));
}
__device__ __forceinline__ void sts_f32(uint32_t a, float v) {
    asm volatile("st.shared.f32 [%0], %1;" :: "r"(a), "f"(v));
}
__device__ __forceinline__ void sts_v2(uint32_t a, float x, float y) {
    asm volatile("st.shared.v2.f32 [%0], {%1, %2};" :: "r"(a), "f"(x), "f"(y));
}
#define LDSM4(r0, r1, r2, r3, addr) \
    asm volatile("ldmatrix.sync.aligned.m8n8.x4.shared.b16 {%0,%1,%2,%3}, [%4];" \
                 : "=r"(r0), "=r"(r1), "=r"(r2), "=r"(r3) : "r"(addr))

__device__ __forceinline__ void mma_bf16(float* d,
    uint32_t a0, uint32_t a1, uint32_t a2, uint32_t a3, uint32_t b0, uint32_t b1) {
    asm volatile("mma.sync.aligned.m16n8k16.row.col.f32.bf16.bf16.f32 "
                 "{%0,%1,%2,%3}, {%4,%5,%6,%7}, {%8,%9}, {%0,%1,%2,%3};"
                 : "+f"(d[0]), "+f"(d[1]), "+f"(d[2]), "+f"(d[3])
                 : "r"(a0), "r"(a1), "r"(a2), "r"(a3), "r"(b0), "r"(b1));
}

__global__ void init_kernel() {
    int i = blockIdx.x * blockDim.x + threadIdx.x;
    if (i < 2 * BB * HH) {
        ((__nv_bfloat16*)g_h0h)[i] = __float2bfloat16(0.0f);
        ((__nv_bfloat16*)g_h0l)[i] = __float2bfloat16(0.0f);
        ((__nv_bfloat16*)g_h1h)[i] = __float2bfloat16(0.0f);
        ((__nv_bfloat16*)g_h1l)[i] = __float2bfloat16(0.0f);
    }
    if (i == 0) { g_count = 0; g_gen = 0; }
}

// weight preconvert: permuted [u][tile][n][k], n = gate*16+j, k over [Wx|Wh]
__global__ void convert_weights_kernel(const float* __restrict__ Wx,
                                       const float* __restrict__ Wh) {
    size_t idx = (size_t)blockIdx.x * blockDim.x + threadIdx.x;
    if (idx >= 2ull * 64 * 64 * 2048) return;
    int k    = idx & 2047;
    int n    = (idx >> 11) & 63;
    int tile = (idx >> 17) & 63;
    int u    = (int)(idx >> 23);
    int gate = n >> 4, j = n & 15;
    int r = gate * 1024 + tile * 16 + j;
    float w = (k < 1024) ? Wx[((size_t)u * 4096 + r) * 1024 + k]
                         : Wh[((size_t)u * 4096 + r) * 1024 + (k - 1024)];
    __nv_bfloat16 hi = __float2bfloat16(w);
    __nv_bfloat16 lo = __float2bfloat16(w - __bfloat162float(hi));
    g_WBh[idx] = hi;
    g_WBl[idx] = lo;
}

__global__ void convert_embed_kernel(const float* __restrict__ embed) {
    int i = blockIdx.x * blockDim.x + threadIdx.x;
    if (i >= VV * DD) return;
    float w = embed[i];
    __nv_bfloat16 hi = __float2bfloat16(w);
    __nv_bfloat16 lo = __float2bfloat16(w - __bfloat162float(hi));
    g_embh[i] = hi;
    g_embl[i] = lo;
}

__device__ __forceinline__ void grid_barrier() {
    __syncthreads();
    if (threadIdx.x == 0) {
        unsigned gen = g_gen;
        __threadfence();
        if (atomicAdd(&g_count, 1u) == NCTA - 1) {
            g_count = 0;
            __threadfence();
            g_gen = gen + 1;
        } else {
            while (g_gen == gen) { __nanosleep(64); }
            __threadfence();
        }
    }
    __syncthreads();
}

// Persistent bf16-split mma.sync LSTM, ldmatrix edition.
// 128 CTAs x 512 thr. CTA: layer u = blockIdx>>6, tile = blockIdx&63 (4 gates x 16 cols).
// Per phase: D[64 batch x 64 n] = A[64 x 2048] x W[64 x 2048]^T, 3-pass bf16 split.
__global__ __launch_bounds__(NTHR, 1) void lstm_persistent_kernel(
    const int* __restrict__ x, const float* __restrict__ bias)
{
    extern __shared__ char sm_raw[];
    const uint32_t sb = smem_u32(sm_raw);

    const int tid  = threadIdx.x;
    const int wid  = tid >> 5;
    const int lane = tid & 31;
    const int u    = blockIdx.x >> 6;
    const int tile = blockIdx.x & 63;
    const int col0 = tile * 16;

    // warp grid 4x4: warp computes m16 x n16
    const int m0 = (wid & 3) * 16;
    const int wn = wid >> 2;
    const int lg = lane >> 2;
    const int t2 = (lane & 3) * 2;

    // ldmatrix lane-address components (byte offsets within a staged array)
    // A (x4: mats (m0-7,k0-7),(m8-15,k0-7),(m0-7,k8-15),(m8-15,k8-15))
    const uint32_t a_lrow = (uint32_t)(m0 + (lane & 7) + ((lane >> 3) & 1) * 8) * PB
                          + ((lane >> 4) & 1) * 16;
    // B (x4: mats (n0-7,k0-7),(n0-7,k8-15),(n8-15,k0-7),(n8-15,k8-15))
    const uint32_t b_lrow = (uint32_t)(wn * 16 + (lane & 7) + ((lane >> 4) & 1) * 8) * PB
                          + ((lane >> 3) & 1) * 16;

    // staging role: q = array (0 AH, 1 AL, 2 BH, 3 BL), r = row, half = lo/hi 128B
    const int q    = tid >> 7;
    const int r    = (tid >> 1) & 63;
    const int half = tid & 1;

    // pointwise role
    const int pj  = tid & 15;
    const int pb0 = tid >> 4;   // 0..31
    const float* bL = bias + u * 4096;
    const float bi_ = bL[0    + col0 + pj];
    const float bf_ = bL[1024 + col0 + pj];
    const float bg_ = bL[2048 + col0 + pj];
    const float bo_ = bL[3072 + col0 + pj];

    for (int i = tid; i < 64 * 17; i += NTHR) sts_f32(sb + SCST + i * 4, 0.0f);
    __syncthreads();

    const __nv_bfloat16* wbh = g_WBh + ((size_t)(u * 64 + tile) * 64) * 2048;
    const __nv_bfloat16* wbl = g_WBl + ((size_t)(u * 64 + tile) * 64) * 2048;

    for (int p = 0; p <= TT; p++) {
        const bool valid = (u == 0) ? (p < TT) : (p >= 1);
        const int  tc    = (u == 0) ? (valid ? p : TT - 1) : (valid ? p - 1 : 0);
        const int  wbuf  = tc & 1;
        const int  rbuf  = (tc + 1) & 1;

        if (tid < BB) sts_u32(sb + STOKS + tid * 4, (uint32_t)x[tid * TT + tc]);
        __syncthreads();

        float acc[2][4];
#pragma unroll
        for (int a = 0; a < 2; a++)
#pragma unroll
            for (int b = 0; b < 4; b++) acc[a][b] = 0.0f;

        // stage chunk c (k in [c*128, c*128+128)) into buffer s
        auto stage_chunk = [&](int c, int s) {
            uint32_t dst = sb + s * STAGE + q * ARR + r * PB + half * 128;
            const __nv_bfloat16* src;
            if (q >= 2) {
                const __nv_bfloat16* base = (q == 2) ? wbh : wbl;
                src = base + (size_t)r * 2048 + c * KC + half * 64;
            } else {
                if (u == 0) {
                    if (c < 8) {
                        int tok = (int)lds_u32(sb + STOKS + r * 4);
                        src = ((q == 0) ? g_embh : g_embl) + (size_t)tok * DD + c * KC + half * 64;
                    } else {
                        src = ((q == 0) ? g_h0h[rbuf][r] : g_h0l[rbuf][r]) + (c - 8) * KC + half * 64;
                    }
                } else {
                    if (c < 8) src = ((q == 0) ? g_h0h[wbuf][r] : g_h0l[wbuf][r]) + c * KC + half * 64;
                    else       src = ((q == 0) ? g_h1h[rbuf][r] : g_h1l[rbuf][r]) + (c - 8) * KC + half * 64;
                }
            }
#pragma unroll
            for (int un = 0; un < 8; un++)
                cp16(dst + un * 16, src + un * 8);
            cp_commit();
        };

        stage_chunk(0, 0);
        for (int c = 0; c < NCH; c++) {
            const int s = c & 1;
            if (c + 1 < NCH) { stage_chunk(c + 1, (c + 1) & 1); cp_wait<1>(); }
            else             { cp_wait<0>(); }
            __syncthreads();

            const uint32_t base = sb + s * STAGE;
            const uint32_t aH = base + AH0 + a_lrow;
            const uint32_t aL = base + AL0 + a_lrow;
            const uint32_t bH = base + BH0 + b_lrow;
            const uint32_t bLo = base + BL0 + b_lrow;
#pragma unroll
            for (int ks = 0; ks < 8; ks++) {
                const uint32_t ko = ks * 32;      // 16 bf16 = 32B per k-step
                uint32_t ah0, ah1, ah2, ah3, al0, al1, al2, al3;
                uint32_t bh0, bh1, bh2, bh3, bl0, bl1, bl2, bl3;
                LDSM4(ah0, ah1, ah2, ah3, aH + ko);
                LDSM4(bh0, bh1, bh2, bh3, bH + ko);
                LDSM4(al0, al1, al2, al3, aL + ko);
                LDSM4(bl0, bl1, bl2, bl3, bLo + ko);
                mma_bf16(acc[0], ah0, ah1, ah2, ah3, bh0, bh1);
                mma_bf16(acc[1], ah0, ah1, ah2, ah3, bh2, bh3);
                mma_bf16(acc[0], ah0, ah1, ah2, ah3, bl0, bl1);
                mma_bf16(acc[1], ah0, ah1, ah2, ah3, bl2, bl3);
                mma_bf16(acc[0], al0, al1, al2, al3, bh0, bh1);
                mma_bf16(acc[1], al0, al1, al2, al3, bh2, bh3);
            }
            __syncthreads();
        }

        // D frags -> gate smem [64 m][68 f32 pitch]
        {
            const uint32_t grow = sb + SGATE + (uint32_t)(m0 + lg) * 272
                                + (uint32_t)(wn * 16 + t2) * 4;
#pragma unroll
            for (int ns = 0; ns < 2; ns++) {
                sts_v2(grow + ns * 32,           acc[ns][0], acc[ns][1]);
                sts_v2(grow + ns * 32 + 8 * 272, acc[ns][2], acc[ns][3]);
            }
        }
        __syncthreads();

        // pointwise: thread owns col j = pj, batches pb0 and pb0+32
        if (valid) {
#pragma unroll
            for (int qq = 0; qq < 2; qq++) {
                const int b   = pb0 + 32 * qq;
                const int col = col0 + pj;
                const uint32_t gaddr = sb + SGATE + b * 272;
                float gi = lds_f32(gaddr + (0  + pj) * 4) + bi_;
                float gf = lds_f32(gaddr + (16 + pj) * 4) + bf_;
                float gg = lds_f32(gaddr + (32 + pj) * 4) + bg_;
                float go = lds_f32(gaddr + (48 + pj) * 4) + bo_;
                const uint32_t caddr = sb + SCST + (b * 17 + pj) * 4;
                float c_old = lds_f32(caddr);
                float c_new = sigf(gf) * c_old + sigf(gi) * tanhf(gg);
                float h_new = sigf(go) * tanhf(c_new);
                sts_f32(caddr, c_new);
                __nv_bfloat16 hh = __float2bfloat16(h_new);
                __nv_bfloat16 hl = __float2bfloat16(h_new - __bfloat162float(hh));
                if (u == 0) {
                    g_h0h[wbuf][b][col] = hh;
                    g_h0l[wbuf][b][col] = hl;
                } else {
                    g_h1h[wbuf][b][col] = hh;
                    g_h1l[wbuf][b][col] = hl;
                    g_Hout[((size_t)b * TT + tc) * HH + col] = h_new;
                }
            }
        }
        grid_barrier();
    }
}

// logits[m, v] = g_Hout[m, :] . Wout[v, :] + bout[v]  (M=32768, N=128, K=1024)
__global__ __launch_bounds__(128) void out_proj_kernel(
    const float* __restrict__ Wout, const float* __restrict__ bout,
    float* __restrict__ out)
{
    __shared__ float As[32][68];
    __shared__ float Ws[32][36];

    const int tid = threadIdx.x;
    const int m0  = blockIdx.x * 64;
    const int v0  = blockIdx.y * 32;
    const int tm  = tid & 15;
    const int tn  = tid >> 4;

    float acc[4][4];
#pragma unroll
    for (int i = 0; i < 4; i++)
#pragma unroll
        for (int j = 0; j < 4; j++) acc[i][j] = 0.0f;

#pragma unroll 1
    for (int k0 = 0; k0 < HH; k0 += 32) {
#pragma unroll
        for (int qy = 0; qy < 4; qy++) {
            int idx = tid + 128 * qy;
            int bb = idx >> 3, kv = idx & 7, k = k0 + kv * 4;
            float4 v = *reinterpret_cast<const float4*>(&g_Hout[(size_t)(m0 + bb) * HH + k]);
            int kr = kv * 4;
            As[kr + 0][bb] = v.x; As[kr + 1][bb] = v.y;
            As[kr + 2][bb] = v.z; As[kr + 3][bb] = v.w;
        }
#pragma unroll
        for (int qy = 0; qy < 2; qy++) {
            int idx = tid + 128 * qy;
            int n = idx >> 3, kv = idx & 7, k = k0 + kv * 4;
            float4 v = *reinterpret_cast<const float4*>(&Wout[(size_t)(v0 + n) * HH + k]);
            int kr = kv * 4;
            Ws[kr + 0][n] = v.x; Ws[kr + 1][n] = v.y;
            Ws[kr + 2][n] = v.z; Ws[kr + 3][n] = v.w;
        }
        __syncthreads();
#pragma unroll
        for (int kk = 0; kk < 32; kk++) {
            float4 a = *reinterpret_cast<const float4*>(&As[kk][tm << 2]);
            float4 w = *reinterpret_cast<const float4*>(&Ws[kk][tn << 2]);
            float av[4] = {a.x, a.y, a.z, a.w};
            float wv[4] = {w.x, w.y, w.z, w.w};
#pragma unroll
            for (int i = 0; i < 4; i++)
#pragma unroll
                for (int j = 0; j < 4; j++)
                    acc[i][j] = fmaf(av[i], wv[j], acc[i][j]);
        }
        __syncthreads();
    }

#pragma unroll
    for (int i = 0; i < 4; i++) {
        int m = m0 + (tm << 2) + i;
#pragma unroll
        for (int j = 0; j < 4; j++) {
            int v = v0 + (tn << 2) + j;
            out[(size_t)m * VV + v] = acc[i][j] + bout[v];
        }
    }
}

extern "C" void kernel_launch(void* const* d_in, const int* in_sizes, int n_in,
                              void* d_out, int out_size)
{
    const int*   x     = (const int*)d_in[0];
    const float* embed = (const float*)d_in[1];
    const float* Wx    = (const float*)d_in[2];
    const float* Wh    = (const float*)d_in[3];
    const float* bias  = (const float*)d_in[4];
    const float* Wout  = (const float*)d_in[5];
    const float* bout  = (const float*)d_in[6];
    float*       out   = (float*)d_out;

    static int smem_set = 0;
    if (!smem_set) {
        cudaFuncSetAttribute(lstm_persistent_kernel,
                             cudaFuncAttributeMaxDynamicSharedMemorySize, SMEM_DYN);
        smem_set = 1;
    }

    init_kernel<<<(2 * BB * HH + 255) / 256, 256>>>();
    convert_weights_kernel<<<(int)((2ull * 64 * 64 * 2048 + 255) / 256), 256>>>(Wx, Wh);
    convert_embed_kernel<<<(VV * DD + 255) / 256, 256>>>(embed);
    lstm_persistent_kernel<<<NCTA, NTHR, SMEM_DYN>>>(x, bias);
    out_proj_kernel<<<dim3(BB * TT / 64, VV / 32), 128>>>(Wout, bout, out);
}

// round 9
// speedup vs baseline: 1.2220x; 1.2220x over previous
#include <cuda_runtime.h>
#include <cuda_bf16.h>
#include <math.h>
#include <stdint.h>

#define BB 64
#define TT 512
#define DD 1024
#define HH 1024
#define VV 128
#define NCTA 128
#define NTHR 512
#define KC 64            // k elements per chunk
#define NCH 32           // chunks per phase (K = 2048)
#define PB 144           // bytes per staged row (64 bf16 + 8 pad)

// ---- dynamic smem layout (byte offsets) ----
#define ARR   9216           // one staged array: 64 rows * 144B
#define STAGE (4 * ARR)      // AH, AL, BH, BL = 36864B per stage
#define NSTG  4
#define AH0   0
#define AL0   ARR
#define BH0   (2 * ARR)
#define BL0   (3 * ARR)
#define SGATE (NSTG * STAGE)           // 147456: f32 [64][68]
#define SCST  (SGATE + 64 * 68 * 4)    // f32 [64][17]
#define STOKS (SCST + 64 * 17 * 4)     // 64 ints
#define SMEM_DYN (STOKS + 256 + 256)

// ---- persistent device scratch ----
__device__ __nv_bfloat16 g_WBh[2ull * 64 * 64 * 2048];  // permuted weights hi
__device__ __nv_bfloat16 g_WBl[2ull * 64 * 64 * 2048];  // permuted weights lo
__device__ __nv_bfloat16 g_embh[VV * DD];
__device__ __nv_bfloat16 g_embl[VV * DD];
__device__ __nv_bfloat16 g_h0h[2][BB][HH];
__device__ __nv_bfloat16 g_h0l[2][BB][HH];
__device__ __nv_bfloat16 g_h1h[2][BB][HH];
__device__ __nv_bfloat16 g_h1l[2][BB][HH];
__device__ float g_Hout[(size_t)BB * TT * HH];
__device__ volatile unsigned g_gen;
__device__ unsigned g_count;

__device__ __forceinline__ float sigf(float v) { return 1.0f / (1.0f + expf(-v)); }

__device__ __forceinline__ uint32_t smem_u32(const void* p) {
    uint32_t a;
    asm("{ .reg .u64 t; cvta.to.shared.u64 t, %1; cvt.u32.u64 %0, t; }" : "=r"(a) : "l"(p));
    return a;
}
__device__ __forceinline__ void cp16(uint32_t dst, const void* src) {
    asm volatile("cp.async.cg.shared.global [%0], [%1], 16;" :: "r"(dst), "l"(src));
}
__device__ __forceinline__ void cp_commit() { asm volatile("cp.async.commit_group;"); }
template<int N> __device__ __forceinline__ void cp_wait() {
    asm volatile("cp.async.wait_group %0;" :: "n"(N));
}
__device__ __forceinline__ uint32_t lds_u32(uint32_t a) {
    uint32_t v; asm volatile("ld.shared.b32 %0, [%1];" : "=r"(v) : "r"(a)); return v;
}
__device__ __forceinline__ float lds_f32(uint32_t a) {
    float v; asm volatile("ld.shared.f32 %0, [%1];" : "=f"(v) : "r"(a)); return v;
}
__device__ __forceinline__ void sts_u32(uint32_t a, uint32_t v) {
    asm volatile("st.shared.b32 [%0], %1;" :: "r"(a), "r"(v));
}
__device__ __forceinline__ void sts_f32(uint32_t a, float v) {
    asm volatile("st.shared.f32 [%0], %1;" :: "r"(a), "f"(v));
}
__device__ __forceinline__ void sts_v2(uint32_t a, float x, float y) {
    asm volatile("st.shared.v2.f32 [%0], {%1, %2};" :: "r"(a), "f"(x), "f"(y));
}
#define LDSM4(r0, r1, r2, r3, addr) \
    asm volatile("ldmatrix.sync.aligned.m8n8.x4.shared.b16 {%0,%1,%2,%3}, [%4];" \
                 : "=r"(r0), "=r"(r1), "=r"(r2), "=r"(r3) : "r"(addr))

__device__ __forceinline__ void mma_bf16(float* d,
    uint32_t a0, uint32_t a1, uint32_t a2, uint32_t a3, uint32_t b0, uint32_t b1) {
    asm volatile("mma.sync.aligned.m16n8k16.row.col.f32.bf16.bf16.f32 "
                 "{%0,%1,%2,%3}, {%4,%5,%6,%7}, {%8,%9}, {%0,%1,%2,%3};"
                 : "+f"(d[0]), "+f"(d[1]), "+f"(d[2]), "+f"(d[3])
                 : "r"(a0), "r"(a1), "r"(a2), "r"(a3), "r"(b0), "r"(b1));
}

__global__ void init_kernel() {
    int i = blockIdx.x * blockDim.x + threadIdx.x;
    if (i < 2 * BB * HH) {
        ((__nv_bfloat16*)g_h0h)[i] = __float2bfloat16(0.0f);
        ((__nv_bfloat16*)g_h0l)[i] = __float2bfloat16(0.0f);
        ((__nv_bfloat16*)g_h1h)[i] = __float2bfloat16(0.0f);
        ((__nv_bfloat16*)g_h1l)[i] = __float2bfloat16(0.0f);
    }
    if (i == 0) { g_count = 0; g_gen = 0; }
}

// weight preconvert: permuted [u][tile][n][k], n = gate*16+j, k over [Wx|Wh]
__global__ void convert_weights_kernel(const float* __restrict__ Wx,
                                       const float* __restrict__ Wh) {
    size_t idx = (size_t)blockIdx.x * blockDim.x + threadIdx.x;
    if (idx >= 2ull * 64 * 64 * 2048) return;
    int k    = idx & 2047;
    int n    = (idx >> 11) & 63;
    int tile = (idx >> 17) & 63;
    int u    = (int)(idx >> 23);
    int gate = n >> 4, j = n & 15;
    int r = gate * 1024 + tile * 16 + j;
    float w = (k < 1024) ? Wx[((size_t)u * 4096 + r) * 1024 + k]
                         : Wh[((size_t)u * 4096 + r) * 1024 + (k - 1024)];
    __nv_bfloat16 hi = __float2bfloat16(w);
    __nv_bfloat16 lo = __float2bfloat16(w - __bfloat162float(hi));
    g_WBh[idx] = hi;
    g_WBl[idx] = lo;
}

__global__ void convert_embed_kernel(const float* __restrict__ embed) {
    int i = blockIdx.x * blockDim.x + threadIdx.x;
    if (i >= VV * DD) return;
    float w = embed[i];
    __nv_bfloat16 hi = __float2bfloat16(w);
    __nv_bfloat16 lo = __float2bfloat16(w - __bfloat162float(hi));
    g_embh[i] = hi;
    g_embl[i] = lo;
}

__device__ __forceinline__ void grid_barrier() {
    __syncthreads();
    if (threadIdx.x == 0) {
        unsigned gen = g_gen;
        __threadfence();
        if (atomicAdd(&g_count, 1u) == NCTA - 1) {
            g_count = 0;
            __threadfence();
            g_gen = gen + 1;
        } else {
            while (g_gen == gen) { __nanosleep(32); }
            __threadfence();
        }
    }
    __syncthreads();
}

// Persistent bf16-split mma.sync LSTM, 4-stage pipelined.
// 128 CTAs x 512 thr. CTA: layer u = blockIdx>>6, tile = blockIdx&63 (4 gates x 16 cols).
// Per phase: D[64 batch x 64 n] = A[64 x 2048] x W[64 x 2048]^T, 3-pass bf16 split.
__global__ __launch_bounds__(NTHR, 1) void lstm_persistent_kernel(
    const int* __restrict__ x, const float* __restrict__ bias)
{
    extern __shared__ char sm_raw[];
    const uint32_t sb = smem_u32(sm_raw);

    const int tid  = threadIdx.x;
    const int wid  = tid >> 5;
    const int lane = tid & 31;
    const int u    = blockIdx.x >> 6;
    const int tile = blockIdx.x & 63;
    const int col0 = tile * 16;

    // warp grid 4x4: warp computes m16 x n16
    const int m0 = (wid & 3) * 16;
    const int wn = wid >> 2;
    const int lg = lane >> 2;
    const int t2 = (lane & 3) * 2;

    // ldmatrix lane addresses (byte offsets within a staged array)
    const uint32_t a_lrow = (uint32_t)(m0 + (lane & 7) + ((lane >> 3) & 1) * 8) * PB
                          + ((lane >> 4) & 1) * 16;
    const uint32_t b_lrow = (uint32_t)(wn * 16 + (lane & 7) + ((lane >> 4) & 1) * 8) * PB
                          + ((lane >> 3) & 1) * 16;

    // staging role: q = array (0 AH act-hi, 1 AL act-lo, 2 BH w-hi, 3 BL w-lo),
    // r = row, half = which 64B of the 128B row
    const int q    = tid >> 7;
    const int r    = (tid >> 1) & 63;
    const int half = tid & 1;

    // pointwise role
    const int pj  = tid & 15;
    const int pb0 = tid >> 4;   // 0..31
    const float* bL = bias + u * 4096;
    const float bi_ = bL[0    + col0 + pj];
    const float bf_ = bL[1024 + col0 + pj];
    const float bg_ = bL[2048 + col0 + pj];
    const float bo_ = bL[3072 + col0 + pj];

    for (int i = tid; i < 64 * 17; i += NTHR) sts_f32(sb + SCST + i * 4, 0.0f);
    __syncthreads();

    const __nv_bfloat16* wbh = g_WBh + ((size_t)(u * 64 + tile) * 64) * 2048;
    const __nv_bfloat16* wbl = g_WBl + ((size_t)(u * 64 + tile) * 64) * 2048;

    for (int p = 0; p <= TT; p++) {
        const bool valid = (u == 0) ? (p < TT) : (p >= 1);
        const int  tc    = (u == 0) ? (valid ? p : TT - 1) : (valid ? p - 1 : 0);
        const int  wbuf  = tc & 1;
        const int  rbuf  = (tc + 1) & 1;

        if (tid < BB) sts_u32(sb + STOKS + tid * 4, (uint32_t)x[tid * TT + tc]);
        __syncthreads();

        float acc[2][4];
#pragma unroll
        for (int a = 0; a < 2; a++)
#pragma unroll
            for (int b = 0; b < 4; b++) acc[a][b] = 0.0f;

        // stage chunk c (k in [c*64, c*64+64)) into ring buffer c&3
        auto stage_chunk = [&](int c) {
            uint32_t dst = sb + (c & 3) * STAGE + q * ARR + r * PB + half * 64;
            const __nv_bfloat16* src;
            if (q >= 2) {
                const __nv_bfloat16* base = (q == 2) ? wbh : wbl;
                src = base + (size_t)r * 2048 + c * KC + half * 32;
            } else {
                if (u == 0) {
                    if (c < 16) {
                        int tok = (int)lds_u32(sb + STOKS + r * 4);
                        src = ((q == 0) ? g_embh : g_embl) + (size_t)tok * DD + c * KC + half * 32;
                    } else {
                        src = ((q == 0) ? g_h0h[rbuf][r] : g_h0l[rbuf][r]) + (c - 16) * KC + half * 32;
                    }
                } else {
                    if (c < 16) src = ((q == 0) ? g_h0h[wbuf][r] : g_h0l[wbuf][r]) + c * KC + half * 32;
                    else        src = ((q == 0) ? g_h1h[rbuf][r] : g_h1l[rbuf][r]) + (c - 16) * KC + half * 32;
                }
            }
#pragma unroll
            for (int un = 0; un < 4; un++)
                cp16(dst + un * 16, src + un * 8);
            cp_commit();
        };

        // prologue: 3 chunks in flight
        stage_chunk(0); stage_chunk(1); stage_chunk(2);

        for (int c = 0; c < NCH; c++) {
            if (c < NCH - 2)       cp_wait<2>();
            else if (c == NCH - 2) cp_wait<1>();
            else                   cp_wait<0>();
            __syncthreads();                    // chunk c visible; compute(c-1) done by all
            if (c + 3 < NCH) stage_chunk(c + 3); // overwrites buffer (c-1)&3 — safe

            const uint32_t base = sb + (c & 3) * STAGE;
            const uint32_t aH  = base + AH0 + a_lrow;
            const uint32_t aL  = base + AL0 + a_lrow;
            const uint32_t bH  = base + BH0 + b_lrow;
            const uint32_t bLo = base + BL0 + b_lrow;
#pragma unroll
            for (int ks = 0; ks < 4; ks++) {
                const uint32_t ko = ks * 32;
                uint32_t ah0, ah1, ah2, ah3, al0, al1, al2, al3;
                uint32_t bh0, bh1, bh2, bh3, bl0, bl1, bl2, bl3;
                LDSM4(ah0, ah1, ah2, ah3, aH + ko);
                LDSM4(bh0, bh1, bh2, bh3, bH + ko);
                LDSM4(al0, al1, al2, al3, aL + ko);
                LDSM4(bl0, bl1, bl2, bl3, bLo + ko);
                mma_bf16(acc[0], ah0, ah1, ah2, ah3, bh0, bh1);
                mma_bf16(acc[1], ah0, ah1, ah2, ah3, bh2, bh3);
                mma_bf16(acc[0], ah0, ah1, ah2, ah3, bl0, bl1);
                mma_bf16(acc[1], ah0, ah1, ah2, ah3, bl2, bl3);
                mma_bf16(acc[0], al0, al1, al2, al3, bh0, bh1);
                mma_bf16(acc[1], al0, al1, al2, al3, bh2, bh3);
            }
        }
        __syncthreads();

        // D frags -> gate smem [64 m][68 f32 pitch]
        {
            const uint32_t grow = sb + SGATE + (uint32_t)(m0 + lg) * 272
                                + (uint32_t)(wn * 16 + t2) * 4;
#pragma unroll
            for (int ns = 0; ns < 2; ns++) {
                sts_v2(grow + ns * 32,           acc[ns][0], acc[ns][1]);
                sts_v2(grow + ns * 32 + 8 * 272, acc[ns][2], acc[ns][3]);
            }
        }
        __syncthreads();

        // pointwise: thread owns col j = pj, batches pb0 and pb0+32
        if (valid) {
#pragma unroll
            for (int qq = 0; qq < 2; qq++) {
                const int b   = pb0 + 32 * qq;
                const int col = col0 + pj;
                const uint32_t gaddr = sb + SGATE + b * 272;
                float gi = lds_f32(gaddr + (0  + pj) * 4) + bi_;
                float gf = lds_f32(gaddr + (16 + pj) * 4) + bf_;
                float gg = lds_f32(gaddr + (32 + pj) * 4) + bg_;
                float go = lds_f32(gaddr + (48 + pj) * 4) + bo_;
                const uint32_t caddr = sb + SCST + (b * 17 + pj) * 4;
                float c_old = lds_f32(caddr);
                float c_new = sigf(gf) * c_old + sigf(gi) * tanhf(gg);
                float h_new = sigf(go) * tanhf(c_new);
                sts_f32(caddr, c_new);
                __nv_bfloat16 hh = __float2bfloat16(h_new);
                __nv_bfloat16 hl = __float2bfloat16(h_new - __bfloat162float(hh));
                if (u == 0) {
                    g_h0h[wbuf][b][col] = hh;
                    g_h0l[wbuf][b][col] = hl;
                } else {
                    g_h1h[wbuf][b][col] = hh;
                    g_h1l[wbuf][b][col] = hl;
                    g_Hout[((size_t)b * TT + tc) * HH + col] = h_new;
                }
            }
        }
        grid_barrier();
    }
}

// logits[m, v] = g_Hout[m, :] . Wout[v, :] + bout[v]  (M=32768, N=128, K=1024)
__global__ __launch_bounds__(128) void out_proj_kernel(
    const float* __restrict__ Wout, const float* __restrict__ bout,
    float* __restrict__ out)
{
    __shared__ float As[32][68];
    __shared__ float Ws[32][36];

    const int tid = threadIdx.x;
    const int m0  = blockIdx.x * 64;
    const int v0  = blockIdx.y * 32;
    const int tm  = tid & 15;
    const int tn  = tid >> 4;

    float acc[4][4];
#pragma unroll
    for (int i = 0; i < 4; i++)
#pragma unroll
        for (int j = 0; j < 4; j++) acc[i][j] = 0.0f;

#pragma unroll 1
    for (int k0 = 0; k0 < HH; k0 += 32) {
#pragma unroll
        for (int qy = 0; qy < 4; qy++) {
            int idx = tid + 128 * qy;
            int bb = idx >> 3, kv = idx & 7, k = k0 + kv * 4;
            float4 v = *reinterpret_cast<const float4*>(&g_Hout[(size_t)(m0 + bb) * HH + k]);
            int kr = kv * 4;
            As[kr + 0][bb] = v.x; As[kr + 1][bb] = v.y;
            As[kr + 2][bb] = v.z; As[kr + 3][bb] = v.w;
        }
#pragma unroll
        for (int qy = 0; qy < 2; qy++) {
            int idx = tid + 128 * qy;
            int n = idx >> 3, kv = idx & 7, k = k0 + kv * 4;
            float4 v = *reinterpret_cast<const float4*>(&Wout[(size_t)(v0 + n) * HH + k]);
            int kr = kv * 4;
            Ws[kr + 0][n] = v.x; Ws[kr + 1][n] = v.y;
            Ws[kr + 2][n] = v.z; Ws[kr + 3][n] = v.w;
        }
        __syncthreads();
#pragma unroll
        for (int kk = 0; kk < 32; kk++) {
            float4 a = *reinterpret_cast<const float4*>(&As[kk][tm << 2]);
            float4 w = *reinterpret_cast<const float4*>(&Ws[kk][tn << 2]);
            float av[4] = {a.x, a.y, a.z, a.w};
            float wv[4] = {w.x, w.y, w.z, w.w};
#pragma unroll
            for (int i = 0; i < 4; i++)
#pragma unroll
                for (int j = 0; j < 4; j++)
                    acc[i][j] = fmaf(av[i], wv[j], acc[i][j]);
        }
        __syncthreads();
    }

#pragma unroll
    for (int i = 0; i < 4; i++) {
        int m = m0 + (tm << 2) + i;
#pragma unroll
        for (int j = 0; j < 4; j++) {
            int v = v0 + (tn << 2) + j;
            out[(size_t)m * VV + v] = acc[i][j] + bout[v];
        }
    }
}

extern "C" void kernel_launch(void* const* d_in, const int* in_sizes, int n_in,
                              void* d_out, int out_size)
{
    const int*   x     = (const int*)d_in[0];
    const float* embed = (const float*)d_in[1];
    const float* Wx    = (const float*)d_in[2];
    const float* Wh    = (const float*)d_in[3];
    const float* bias  = (const float*)d_in[4];
    const float* Wout  = (const float*)d_in[5];
    const float* bout  = (const float*)d_in[6];
    float*       out   = (float*)d_out;

    static int smem_set = 0;
    if (!smem_set) {
        cudaFuncSetAttribute(lstm_persistent_kernel,
                             cudaFuncAttributeMaxDynamicSharedMemorySize, SMEM_DYN);
        smem_set = 1;
    }

    init_kernel<<<(2 * BB * HH + 255) / 256, 256>>>();
    convert_weights_kernel<<<(int)((2ull * 64 * 64 * 2048 + 255) / 256), 256>>>(Wx, Wh);
    convert_embed_kernel<<<(VV * DD + 255) / 256, 256>>>(embed);
    lstm_persistent_kernel<<<NCTA, NTHR, SMEM_DYN>>>(x, bias);
    out_proj_kernel<<<dim3(BB * TT / 64, VV / 32), 128>>>(Wout, bout, out);
}